// round 5
// baseline (speedup 1.0000x reference)
#include <cuda_runtime.h>
#include <cuda_fp16.h>
#include <math.h>
#include <stdint.h>

#define NKC 1024
#define F   128
#define BM  64
#define NT  128

// ---- global scratch (no allocations allowed) ----
__device__ __align__(16) unsigned short g_Bh[NKC*F];   // kcWh hi, mma-B-fragment packed
__device__ __align__(16) unsigned short g_Bl[NKC*F];   // kcWh lo
__device__ __align__(16) unsigned int   g_Ehg[F*F/2];  // E hi, fragment packed (u32 pairs)
__device__ __align__(16) unsigned int   g_Elg[F*F/2];  // E lo
__device__ float g_q[NKC];
__device__ float g_v1[F];
__device__ float g_qmax;

// ---- smem offsets (bytes) ----
#define OFF_EXH 0        // ex hi [64][136] fp16 (prologue/Eh phase)
#define OFF_EXL 17408    // ex lo
#define OFF_WH  0        // w hi [64][72] fp16 (ATT loop, aliases ex)
#define OFF_WL  9216     // w lo
#define OFF_B   18432    // B chunk hi, fragment packed, 16KB
#define OFF_BL  34816    // B chunk lo, 16KB
#define OFF_Q   51200    // 1024 f32
#define OFF_RED 55296    // 128 f32
#define OFF_INV 55808    // 64 f32
#define OFF_P   56064    // 64 f32
#define OFF_M   56320    // 64 f32
#define SMEM_SZ 56832

// ---- helpers ----
__device__ __forceinline__ uint32_t smem_u32(const void* p){
  uint32_t a;
  asm("{ .reg .u64 t; cvta.to.shared.u64 t, %1; cvt.u32.u64 %0, t; }" : "=r"(a) : "l"(p));
  return a;
}
__device__ __forceinline__ void mma16816(float* c, const uint32_t* a, uint32_t b0, uint32_t b1){
  asm volatile("mma.sync.aligned.m16n8k16.row.col.f32.f16.f16.f32 "
    "{%0,%1,%2,%3}, {%4,%5,%6,%7}, {%8,%9}, {%0,%1,%2,%3};"
    : "+f"(c[0]), "+f"(c[1]), "+f"(c[2]), "+f"(c[3])
    : "r"(a[0]), "r"(a[1]), "r"(a[2]), "r"(a[3]), "r"(b0), "r"(b1));
}
__device__ __forceinline__ void ldmx4(uint32_t* a, uint32_t addr){
  asm volatile("ldmatrix.sync.aligned.m8n8.x4.shared.b16 {%0,%1,%2,%3}, [%4];"
    : "=r"(a[0]), "=r"(a[1]), "=r"(a[2]), "=r"(a[3]) : "r"(addr));
}
__device__ __forceinline__ void cpa16(uint32_t s, const void* g){
  asm volatile("cp.async.cg.shared.global [%0], [%1], 16;"
    :: "r"(s), "l"((unsigned long long)__cvta_generic_to_global(g)) : "memory");
}
__device__ __forceinline__ uint32_t hpack(__half a, __half b){
  return (uint32_t)__half_as_ushort(a) | ((uint32_t)__half_as_ushort(b) << 16);
}
__device__ __forceinline__ float eluf(float x){ return x > 0.f ? x : (__expf(x) - 1.f); }

// ===========================================================================
// prep_kc: blocks 0..127: kcWh = kc_h @ W1 (fp32), q[j] = kcWh[j].a2,
//          fp16 hi/lo split written fragment-packed to g_Bh/g_Bl.
//          blocks 128..135: E fragment-packed to g_Ehg/g_Elg.
// ===========================================================================
__global__ void __launch_bounds__(256) prep_kc(const float* __restrict__ kch,
    const float* __restrict__ W1, const float* __restrict__ E, const float* __restrict__ a){
  __shared__ float skc[8*F];
  int tid = threadIdx.x;
  if (blockIdx.x < 128){
    int j0 = blockIdx.x * 8;
    ((float4*)skc)[tid] = ((const float4*)(kch + (size_t)j0*F))[tid];
    __syncthreads();
    int jj = tid >> 5, lane = tid & 31, f0 = lane * 4;
    const float* kr = skc + jj*F;
    float a0=0.f, a1=0.f, a2=0.f, a3=0.f;
    #pragma unroll 8
    for (int k = 0; k < F; k++){
      float4 w4 = __ldg((const float4*)(W1 + (size_t)k*F) + lane);
      float s = kr[k];
      a0 = fmaf(s, w4.x, a0); a1 = fmaf(s, w4.y, a1);
      a2 = fmaf(s, w4.z, a2); a3 = fmaf(s, w4.w, a3);
    }
    float qp = a0*__ldg(a+F+f0) + a1*__ldg(a+F+f0+1) + a2*__ldg(a+F+f0+2) + a3*__ldg(a+F+f0+3);
    #pragma unroll
    for (int o = 16; o > 0; o >>= 1) qp += __shfl_xor_sync(0xffffffffu, qp, o);
    if (lane == 0) g_q[j0 + jj] = qp;
    // fragment-packed store
    int j = j0 + jj;
    int t = j >> 6, jj6 = j & 63, kt = jj6 >> 4, kpos = jj6 & 15;
    int rr = kpos >> 3, h = kpos & 1, lk = (kpos & 7) >> 1;
    int cb = (t*4 + kt) * 16;
    #pragma unroll
    for (int u = 0; u < 4; u++){
      float v = (u==0)?a0:(u==1)?a1:(u==2)?a2:a3;
      __half hh = __float2half_rn(v);
      __half ll = __float2half_rn(v - __half2float(hh));
      int f = f0 + u, nt = f >> 3, npos = f & 7;
      int lane_b = npos*4 + lk;
      int idx = ((cb + nt)*32 + lane_b)*4 + rr*2 + h;
      g_Bh[idx] = __half_as_ushort(hh);
      g_Bl[idx] = __half_as_ushort(ll);
    }
  } else {
    int kt = blockIdx.x - 128;          // 0..7
    int n = tid & 127, kg = tid >> 7;   // kg = reg index r
    int nt = n >> 3, npos = n & 7;
    int base = (kt*16 + nt)*32 + npos*4;
    #pragma unroll
    for (int q = 0; q < 4; q++){
      int k0 = kt*16 + kg*8 + 2*q;
      float e0 = __ldg(E + (size_t)k0*F + n);
      float e1 = __ldg(E + (size_t)(k0+1)*F + n);
      __half h0 = __float2half_rn(e0), h1 = __float2half_rn(e1);
      __half l0 = __float2half_rn(e0 - __half2float(h0));
      __half l1 = __float2half_rn(e1 - __half2float(h1));
      int uidx = (base + q)*2 + kg;
      g_Ehg[uidx] = hpack(h0, h1);
      g_Elg[uidx] = hpack(l0, l1);
    }
  }
}

__global__ void prep_v(const float* __restrict__ W1, const float* __restrict__ a){
  __shared__ float red[4];
  int k = threadIdx.x;  // 128
  float v = 0.f;
  #pragma unroll 16
  for (int f = 0; f < F; f++) v = fmaf(W1[(size_t)k*F + f], a[f], v);
  g_v1[k] = v;
  float mq = -3.0e38f;
  #pragma unroll
  for (int i = 0; i < 8; i++) mq = fmaxf(mq, g_q[k + i*128]);
  #pragma unroll
  for (int o = 16; o > 0; o >>= 1) mq = fmaxf(mq, __shfl_xor_sync(0xffffffffu, mq, o));
  if ((k & 31) == 0) red[k >> 5] = mq;
  __syncthreads();
  if (k == 0) g_qmax = fmaxf(fmaxf(red[0], red[1]), fmaxf(red[2], red[3]));
}

// ===========================================================================
// Main kernel: BM=64 rows/CTA, 128 threads (4 warps x 16-row stripes).
// ===========================================================================
__global__ void __launch_bounds__(NT, 2) gat_main(
    const float* __restrict__ exh, const int* __restrict__ adj,
    float* __restrict__ out, int nex)
{
  extern __shared__ __align__(16) char sm[];
  const uint32_t sb = smem_u32(sm);
  float* sQ   = (float*)(sm + OFF_Q);
  float* sRed = (float*)(sm + OFF_RED);
  float* sInv = (float*)(sm + OFF_INV);
  float* sP   = (float*)(sm + OFF_P);
  float* sM   = (float*)(sm + OFF_M);

  const int tid = threadIdx.x;
  const int wp = tid >> 5, lane = tid & 31;
  const int rw = tid >> 1, hf = tid & 1;
  const int row_start = blockIdx.x * BM;
  int rg = row_start + rw; if (rg > nex-1) rg = nex-1;

  // ---- prologue: ex row -> fp16 hi/lo smem + p partial; q -> smem ----
  {
    const float4* src = (const float4*)(exh + (size_t)rg*F + hf*64);
    uint32_t* exH = (uint32_t*)(sm + OFF_EXH);
    uint32_t* exL = (uint32_t*)(sm + OFF_EXL);
    const float* v1p = g_v1 + hf*64;
    float p = 0.f;
    #pragma unroll
    for (int u = 0; u < 16; u++){
      float4 v = src[u];
      p = fmaf(v.x, __ldg(v1p+u*4),   p); p = fmaf(v.y, __ldg(v1p+u*4+1), p);
      p = fmaf(v.z, __ldg(v1p+u*4+2), p); p = fmaf(v.w, __ldg(v1p+u*4+3), p);
      __half hx = __float2half_rn(v.x), hy = __float2half_rn(v.y);
      __half hz = __float2half_rn(v.z), hw = __float2half_rn(v.w);
      int b = rw*68 + hf*32 + u*2;
      exH[b]   = hpack(hx, hy);
      exH[b+1] = hpack(hz, hw);
      exL[b]   = hpack(__float2half_rn(v.x - __half2float(hx)), __float2half_rn(v.y - __half2float(hy)));
      exL[b+1] = hpack(__float2half_rn(v.z - __half2float(hz)), __float2half_rn(v.w - __half2float(hw)));
    }
    sRed[tid] = p;
    ((float4*)sQ)[tid]       = ((const float4*)g_q)[tid];
    ((float4*)sQ)[tid + 128] = ((const float4*)g_q)[tid + 128];
  }
  __syncthreads();
  if (tid < BM){
    float p = sRed[2*tid] + sRed[2*tid+1];
    sP[tid] = p;
    float x = p + g_qmax;
    sM[tid] = fmaxf(x, 0.2f*x);
  }
  __syncthreads();
  const float pr = sP[rw], mr = sM[rw];

  // ---- Eh GEMM: ehAcc = ex @ E (fp16 3-pass), B fragments from global (L2) ----
  float ehAcc[16][4];
  #pragma unroll
  for (int nt = 0; nt < 16; nt++){ ehAcc[nt][0]=0.f; ehAcc[nt][1]=0.f; ehAcc[nt][2]=0.f; ehAcc[nt][3]=0.f; }
  {
    const uint2* geh = (const uint2*)g_Ehg;
    const uint2* gel = (const uint2*)g_Elg;
    #pragma unroll
    for (int kt = 0; kt < 8; kt++){
      uint32_t Ah[4], Al[4];
      uint32_t ad = sb + OFF_EXH + (uint32_t)(((wp*16 + (lane&15))*136 + kt*16 + (lane>>4)*8) * 2);
      ldmx4(Ah, ad);
      ldmx4(Al, ad + (OFF_EXL - OFF_EXH));
      #pragma unroll
      for (int nt = 0; nt < 16; nt++){
        uint2 bh = __ldg(&geh[(kt*16+nt)*32 + lane]);
        uint2 bl = __ldg(&gel[(kt*16+nt)*32 + lane]);
        mma16816(ehAcc[nt], Ah, bh.x, bh.y);
        mma16816(ehAcc[nt], Ah, bl.x, bl.y);
        mma16816(ehAcc[nt], Al, bh.x, bh.y);
      }
    }
  }
  __syncthreads();   // ex smem dead; region becomes w tiles

  // ---- ATT loop ----
  float att[16][4];
  #pragma unroll
  for (int nt = 0; nt < 16; nt++){ att[nt][0]=0.f; att[nt][1]=0.f; att[nt][2]=0.f; att[nt][3]=0.f; }

  const int4* aptr = (const int4*)(adj + (size_t)rg*NKC + hf*32);
  int4 apf[8];
  #pragma unroll
  for (int u = 0; u < 8; u++) apf[u] = __ldg(aptr + u);

  uint32_t* wH = (uint32_t*)(sm + OFF_WH);
  uint32_t* wL = (uint32_t*)(sm + OFF_WL);
  float lp = 0.f;

  for (int t = 0; t < 16; t++){
    // B chunk via cp.async (fragment-packed, linear)
    {
      uint32_t db = sb + OFF_B  + (uint32_t)tid*128;
      uint32_t dl = sb + OFF_BL + (uint32_t)tid*128;
      const char* gb = (const char*)g_Bh + (size_t)t*16384 + tid*128;
      const char* gl = (const char*)g_Bl + (size_t)t*16384 + tid*128;
      #pragma unroll
      for (int u = 0; u < 8; u++){ cpa16(db + u*16, gb + u*16); cpa16(dl + u*16, gl + u*16); }
      asm volatile("cp.async.commit_group;" ::: "memory");
    }
    // w production (fp16 hi/lo)
    {
      const float4* q4 = (const float4*)(sQ + t*64 + hf*32);
      #pragma unroll
      for (int u = 0; u < 8; u++){
        int4 a4 = apf[u];
        float4 qv = q4[u];
        float x0 = pr + qv.x, x1 = pr + qv.y, x2 = pr + qv.z, x3 = pr + qv.w;
        float e0 = fmaxf(x0, 0.2f*x0), e1 = fmaxf(x1, 0.2f*x1);
        float e2 = fmaxf(x2, 0.2f*x2), e3 = fmaxf(x3, 0.2f*x3);
        float w0 = (a4.x > 0) ? __expf(e0 - mr) : 0.f;
        float w1 = (a4.y > 0) ? __expf(e1 - mr) : 0.f;
        float w2 = (a4.z > 0) ? __expf(e2 - mr) : 0.f;
        float w3 = (a4.w > 0) ? __expf(e3 - mr) : 0.f;
        lp += (w0 + w1) + (w2 + w3);
        __half h0 = __float2half_rn(w0), h1 = __float2half_rn(w1);
        __half h2 = __float2half_rn(w2), h3 = __float2half_rn(w3);
        int b = rw*36 + hf*16 + u*2;
        wH[b]   = hpack(h0, h1);
        wH[b+1] = hpack(h2, h3);
        wL[b]   = hpack(__float2half_rn(w0 - __half2float(h0)), __float2half_rn(w1 - __half2float(h1)));
        wL[b+1] = hpack(__float2half_rn(w2 - __half2float(h2)), __float2half_rn(w3 - __half2float(h3)));
      }
    }
    // adj prefetch for next chunk
    if (t < 15){
      #pragma unroll
      for (int u = 0; u < 8; u++) apf[u] = __ldg(aptr + (t+1)*16 + u);
    }
    asm volatile("cp.async.wait_group 0;" ::: "memory");
    __syncthreads();
    // MMA phase
    {
      const uint2* sBh = (const uint2*)(sm + OFF_B);
      const uint2* sBl = (const uint2*)(sm + OFF_BL);
      #pragma unroll
      for (int kt = 0; kt < 4; kt++){
        uint32_t Ah[4], Al[4];
        uint32_t ad = sb + OFF_WH + (uint32_t)(((wp*16 + (lane&15))*72 + kt*16 + (lane>>4)*8) * 2);
        ldmx4(Ah, ad);
        ldmx4(Al, ad + (OFF_WL - OFF_WH));
        #pragma unroll
        for (int nt = 0; nt < 16; nt++){
          uint2 bh = sBh[(kt*16+nt)*32 + lane];
          uint2 bl = sBl[(kt*16+nt)*32 + lane];
          mma16816(att[nt], Ah, bh.x, bh.y);
          mma16816(att[nt], Ah, bl.x, bl.y);
          mma16816(att[nt], Al, bh.x, bh.y);
        }
      }
    }
    __syncthreads();
  }

  // ---- softmax denominators ----
  sRed[tid] = lp;
  __syncthreads();
  if (tid < BM) sInv[tid] = 1.f / (sRed[2*tid] + sRed[2*tid+1]);
  __syncthreads();

  // ---- epilogue ----
  {
    const int r0 = wp*16 + (lane >> 2), r1 = r0 + 8;
    const float i0 = sInv[r0], i1 = sInv[r1];
    const int o0 = row_start + r0, o1 = row_start + r1;
    #pragma unroll
    for (int nt = 0; nt < 16; nt++){
      int col = nt*8 + (lane & 3)*2;
      if (o0 < nex){
        float2 v;
        v.x = eluf(att[nt][0] * i0 * ehAcc[nt][0]);
        v.y = eluf(att[nt][1] * i0 * ehAcc[nt][1]);
        *(float2*)(out + (size_t)o0*F + col) = v;
      }
      if (o1 < nex){
        float2 v;
        v.x = eluf(att[nt][2] * i1 * ehAcc[nt][2]);
        v.y = eluf(att[nt][3] * i1 * ehAcc[nt][3]);
        *(float2*)(out + (size_t)o1*F + col) = v;
      }
    }
  }
}

// ---------------------------------------------------------------------------
extern "C" void kernel_launch(void* const* d_in, const int* in_sizes, int n_in,
                              void* d_out, int out_size)
{
  const float* exh = (const float*)d_in[0];
  const float* kch = (const float*)d_in[1];
  const int*   adj = (const int*)  d_in[2];
  const float* W1  = (const float*)d_in[3];
  const float* E   = (const float*)d_in[4];
  const float* a   = (const float*)d_in[5];
  float* out = (float*)d_out;
  int nex = in_sizes[0] / F;

  prep_kc<<<136, 256>>>(kch, W1, E, a);
  prep_v<<<1, 128>>>(W1, a);

  cudaFuncSetAttribute(gat_main, cudaFuncAttributeMaxDynamicSharedMemorySize, SMEM_SZ);
  gat_main<<<(nex + BM - 1) / BM, NT, SMEM_SZ>>>(exh, adj, out, nex);
}